// round 6
// baseline (speedup 1.0000x reference)
#include <cuda_runtime.h>

#define BB 4
#define NN 4096
#define HH 16
#define DD 64
#define HD (HH*DD)          // 1024
#define BH (BB*HH)          // 64
#define CH 16
#define CHTOK (NN/CH)       // 256
#define EPSZ 1e-6f

#define KVSTR 72            // ==8 mod 32: conflict-free frags (8*ac+ar)
#define QSTR  68            // ==4 mod 32: conflict-free frags (4*ar+ac)
#define CSTR  72

__device__ float g_KVpart[CH*BH*DD*DD];   // 16 MB
__device__ float g_KSpart[CH*BH*DD];
__device__ float g_C[BH*DD*DD];           // tf32-pre-rounded by fold
__device__ float g_Ksum[BH*DD];

__device__ __forceinline__ float phi(float x) { return x > 0.0f ? x + 1.0f : __expf(x); }

__device__ __forceinline__ float tf32r(float x) {
    unsigned u;
    asm("cvt.rna.tf32.f32 %0, %1;" : "=r"(u) : "f"(x));
    return __uint_as_float(u);
}
__device__ __forceinline__ float4 phi4(float4 v) {
    float4 r; r.x = phi(v.x); r.y = phi(v.y); r.z = phi(v.z); r.w = phi(v.w);
    return r;
}
__device__ __forceinline__ float4 r4(float4 v) {
    float4 r; r.x = tf32r(v.x); r.y = tf32r(v.y); r.z = tf32r(v.z); r.w = tf32r(v.w);
    return r;
}

__device__ __forceinline__ void mma_tf32(float c[4],
    unsigned a0, unsigned a1, unsigned a2, unsigned a3,
    unsigned b0, unsigned b1)
{
    asm volatile(
        "mma.sync.aligned.m16n8k8.row.col.f32.tf32.tf32.f32 "
        "{%0,%1,%2,%3},{%4,%5,%6,%7},{%8,%9},{%0,%1,%2,%3};"
        : "+f"(c[0]), "+f"(c[1]), "+f"(c[2]), "+f"(c[3])
        : "r"(a0), "r"(a1), "r"(a2), "r"(a3), "r"(b0), "r"(b1));
}
__device__ __forceinline__ unsigned fb(float x) { return __float_as_uint(x); }

__device__ __forceinline__ void cpa16(void* smem, const void* g) {
    unsigned s = (unsigned)__cvta_generic_to_shared(smem);
    asm volatile("cp.async.ca.shared.global [%0], [%1], 16;" :: "r"(s), "l"(g));
}
#define CP_COMMIT() asm volatile("cp.async.commit_group;")
#define CP_WAIT0()  asm volatile("cp.async.wait_group 0;")

// ---------------------------------------------------------------------------
// Phase 1: partial KV[d][m] = sum_t phi(K[t][d]) * V[t][m], tf32 MMA.
// 2-stage cp.async pipeline, ONE barrier per tile, Ksum accumulated in
// registers during the RMW convert. 1024 blocks x 256 threads.
// ---------------------------------------------------------------------------
__global__ __launch_bounds__(256) void kv_partial_kernel(
    const float* __restrict__ key, const float* __restrict__ value)
{
    __shared__ float Ks[2][32][KVSTR];
    __shared__ float Vs[2][32][KVSTR];
    __shared__ float kpart[16][64];

    const int bx  = blockIdx.x;
    const int c   = bx % CH;
    const int bh  = bx / CH;
    const int b   = bh / HH;
    const int h   = bh % HH;
    const int tid = threadIdx.x;
    const int lane = tid & 31, warp = tid >> 5;
    const int dRow = (warp & 3) * 16;
    const int mCol = (warp >> 2) * 32;
    const int ar = lane >> 2;
    const int ac = lane & 3;

    const int t0i = tid >> 4;        // 0..15
    const int t1i = t0i + 16;
    const int d4  = (tid & 15) * 4;

    const int n0 = c * CHTOK;
    const size_t gbase = (size_t)(b * NN + n0) * HD + h * DD + d4;
    const float* kp0 = key   + gbase + (size_t)t0i * HD;
    const float* kp1 = key   + gbase + (size_t)t1i * HD;
    const float* vp0 = value + gbase + (size_t)t0i * HD;
    const float* vp1 = value + gbase + (size_t)t1i * HD;

    float acc[4][4];
#pragma unroll
    for (int nt = 0; nt < 4; nt++)
#pragma unroll
        for (int j = 0; j < 4; j++) acc[nt][j] = 0.0f;

    float4 ks4 = make_float4(0.f, 0.f, 0.f, 0.f);

    // prologue: tile 0 -> stage 0
    cpa16(&Ks[0][t0i][d4], kp0);
    cpa16(&Ks[0][t1i][d4], kp1);
    cpa16(&Vs[0][t0i][d4], vp0);
    cpa16(&Vs[0][t1i][d4], vp1);
    CP_COMMIT();

    const int NT = CHTOK / 32;
    for (int tile = 0; tile < NT; tile++) {
        const int cur = tile & 1;
        CP_WAIT0();

        // RMW convert own chunks; accumulate Ksum partials from registers
        {
            const float4 p0 = phi4(*(const float4*)&Ks[cur][t0i][d4]);
            const float4 p1 = phi4(*(const float4*)&Ks[cur][t1i][d4]);
            *(float4*)&Ks[cur][t0i][d4] = r4(p0);
            *(float4*)&Ks[cur][t1i][d4] = r4(p1);
            ks4.x += p0.x + p1.x; ks4.y += p0.y + p1.y;
            ks4.z += p0.z + p1.z; ks4.w += p0.w + p1.w;
            *(float4*)&Vs[cur][t0i][d4] = r4(*(const float4*)&Vs[cur][t0i][d4]);
            *(float4*)&Vs[cur][t1i][d4] = r4(*(const float4*)&Vs[cur][t1i][d4]);
        }
        __syncthreads();   // RMW(cur) done for all; MMA(tile-1) done for all

        if (tile + 1 < NT) {
            const size_t off = (size_t)(tile + 1) * 32 * HD;
            const int nxt = cur ^ 1;
            cpa16(&Ks[nxt][t0i][d4], kp0 + off);
            cpa16(&Ks[nxt][t1i][d4], kp1 + off);
            cpa16(&Vs[nxt][t0i][d4], vp0 + off);
            cpa16(&Vs[nxt][t1i][d4], vp1 + off);
            CP_COMMIT();
        }

#pragma unroll
        for (int kk = 0; kk < 4; kk++) {
            const int k0 = kk * 8;
            const unsigned a0 = fb(Ks[cur][k0 + ac    ][dRow + ar    ]);
            const unsigned a1 = fb(Ks[cur][k0 + ac    ][dRow + ar + 8]);
            const unsigned a2 = fb(Ks[cur][k0 + ac + 4][dRow + ar    ]);
            const unsigned a3 = fb(Ks[cur][k0 + ac + 4][dRow + ar + 8]);
#pragma unroll
            for (int nt = 0; nt < 4; nt++) {
                const int nc = mCol + nt * 8 + ar;
                const unsigned b0 = fb(Vs[cur][k0 + ac    ][nc]);
                const unsigned b1 = fb(Vs[cur][k0 + ac + 4][nc]);
                mma_tf32(acc[nt], a0, a1, a2, a3, b0, b1);
            }
        }
    }
    __syncthreads();

    // Ksum reduce: each thread owns unique (t0i, d4) partial
    *(float4*)&kpart[t0i][d4] = ks4;
    __syncthreads();
    if (tid < 64) {
        float s = 0.0f;
#pragma unroll
        for (int r = 0; r < 16; r++) s += kpart[r][tid];
        g_KSpart[(c * BH + bh) * DD + tid] = s;
    }

    float* outp = g_KVpart + (size_t)(c * BH + bh) * DD * DD;
#pragma unroll
    for (int nt = 0; nt < 4; nt++) {
        const int col = mCol + nt * 8 + 2 * ac;
        const int r0  = dRow + ar;
        *(float2*)(outp + r0 * DD + col)       = make_float2(acc[nt][0], acc[nt][1]);
        *(float2*)(outp + (r0 + 8) * DD + col) = make_float2(acc[nt][2], acc[nt][3]);
    }
}

// ---------------------------------------------------------------------------
// Phase 1.5: reduce chunk partials; fold projection. Stores C tf32-ROUNDED
// so phase 2 needs no conversion on C.
// ---------------------------------------------------------------------------
__global__ __launch_bounds__(256) void fold_kernel(const float* __restrict__ W_out)
{
    __shared__ float KVs[DD][68];
    __shared__ float Ws[DD][68];

    const int bh  = blockIdx.x;
    const int h   = bh % HH;
    const int tid = threadIdx.x;
    const int ty  = tid >> 4;
    const int tx  = tid & 15;

#pragma unroll
    for (int i = 0; i < 4; i++) {
        const int lin = (tid + i * 256) * 4;
        float4 s = make_float4(0.f, 0.f, 0.f, 0.f);
#pragma unroll
        for (int cc = 0; cc < CH; cc++) {
            const float4 p = *(const float4*)(g_KVpart + (size_t)(cc * BH + bh) * DD * DD + lin);
            s.x += p.x; s.y += p.y; s.z += p.z; s.w += p.w;
        }
        const int d = lin >> 6, m = lin & 63;
        *(float4*)&KVs[d][m] = s;
    }
#pragma unroll
    for (int i = 0; i < 4; i++) {
        const int lin = (tid + i * 256) * 4;
        const int j = lin >> 6, m = lin & 63;
        *(float4*)&Ws[j][m] = *(const float4*)(W_out + (size_t)j * HD + h * DD + m);
    }
    if (tid < 64) {
        float s = 0.0f;
#pragma unroll
        for (int cc = 0; cc < CH; cc++) s += g_KSpart[(cc * BH + bh) * DD + tid];
        g_Ksum[bh * DD + tid] = s;
    }
    __syncthreads();

    float acc[4][4];
#pragma unroll
    for (int i = 0; i < 4; i++)
#pragma unroll
        for (int j = 0; j < 4; j++) acc[i][j] = 0.0f;

#pragma unroll 4
    for (int m = 0; m < 64; m++) {
        float a[4], w[4];
#pragma unroll
        for (int i = 0; i < 4; i++) a[i] = KVs[ty * 4 + i][m];
#pragma unroll
        for (int j = 0; j < 4; j++) w[j] = Ws[tx * 4 + j][m];
#pragma unroll
        for (int i = 0; i < 4; i++)
#pragma unroll
            for (int j = 0; j < 4; j++) acc[i][j] += a[i] * w[j];
    }

    float* cp = g_C + (size_t)bh * DD * DD;
#pragma unroll
    for (int i = 0; i < 4; i++) {
        float4 w = make_float4(tf32r(acc[i][0]), tf32r(acc[i][1]),
                               tf32r(acc[i][2]), tf32r(acc[i][3]));
        *(float4*)(cp + (ty * 4 + i) * DD + tx * 4) = w;
    }
}

// ---------------------------------------------------------------------------
// Phase 2: out[t][j] = b[j] + sum_h Z[t,h] * (Qphi[t,h,:] @ C[b,h][:,j])
// 2-stage cp.async pipeline over heads (Q and C), ONE barrier per head.
// phi/cvt + Z-dot via RMW of own chunks; dsum double-buffered; Z applied
// to the per-head MMA result in registers. 256 blocks x 256 threads.
// ---------------------------------------------------------------------------
__global__ __launch_bounds__(256) void out_kernel(
    const float* __restrict__ query, const float* __restrict__ b_out,
    float* __restrict__ out)
{
    __shared__ float Qp[2][64][QSTR];
    __shared__ float Cs[2][64][CSTR];
    __shared__ float dsum[2][64];

    const int blk = blockIdx.x;
    const int b   = blk / (NN / 64);
    const int t0g = blk * 64;
    const int tid = threadIdx.x;
    const int lane = tid & 31, warp = tid >> 5;
    const int tRow = (warp & 3) * 16;
    const int jCol = (warp >> 2) * 32;
    const int ar = lane >> 2;
    const int ac = lane & 3;

    const int trow = tid >> 4;       // 0..15 (chunk row base)
    const int cd4  = (tid & 15) * 4;

    // per-chunk global bases (head 0); head h adds h*DD (Q) / h*DD*DD (C)
    const float* qb = query + (size_t)(t0g + trow) * HD + cd4;
    const float* cb = g_C + (size_t)(b * HH) * DD * DD + trow * DD + cd4;
    const float* kb = g_Ksum + (b * HH) * DD + cd4;

    float acc[4][4];
#pragma unroll
    for (int nt = 0; nt < 4; nt++)
#pragma unroll
        for (int j = 0; j < 4; j++) acc[nt][j] = 0.0f;

    // prologue: head 0 -> stage 0
#pragma unroll
    for (int i = 0; i < 4; i++) {
        cpa16(&Qp[0][trow + i * 16][cd4], qb + (size_t)i * 16 * HD);
        cpa16(&Cs[0][trow + i * 16][cd4], cb + i * 16 * DD);
    }
    CP_COMMIT();

    for (int h = 0; h < HH; h++) {
        const int cur = h & 1;
        CP_WAIT0();

        const float4 ksv = *(const float4*)(kb + h * DD);
        // RMW convert Q chunks; per-token dot via half-warp shfl
#pragma unroll
        for (int i = 0; i < 4; i++) {
            const int t = trow + i * 16;
            const float4 p = phi4(*(const float4*)&Qp[cur][t][cd4]);
            *(float4*)&Qp[cur][t][cd4] = r4(p);
            float partial = p.x * ksv.x + p.y * ksv.y + p.z * ksv.z + p.w * ksv.w;
#pragma unroll
            for (int off = 8; off >= 1; off >>= 1)
                partial += __shfl_xor_sync(0xffffffffu, partial, off);
            if ((lane & 15) == 0) dsum[cur][t] = partial;
        }
        __syncthreads();   // RMW(cur) visible; MMA(h-1) done for all warps

        if (h + 1 < HH) {
            const int nxt = cur ^ 1;
#pragma unroll
            for (int i = 0; i < 4; i++) {
                cpa16(&Qp[nxt][trow + i * 16][cd4],
                      qb + (h + 1) * DD + (size_t)i * 16 * HD);
                cpa16(&Cs[nxt][trow + i * 16][cd4],
                      cb + (size_t)(h + 1) * DD * DD + i * 16 * DD);
            }
            CP_COMMIT();
        }

        float tacc[4][4];
#pragma unroll
        for (int nt = 0; nt < 4; nt++)
#pragma unroll
            for (int j = 0; j < 4; j++) tacc[nt][j] = 0.0f;

#pragma unroll
        for (int kk = 0; kk < 8; kk++) {
            const int k0 = kk * 8;
            const unsigned a0 = fb(Qp[cur][tRow + ar    ][k0 + ac    ]);
            const unsigned a1 = fb(Qp[cur][tRow + ar + 8][k0 + ac    ]);
            const unsigned a2 = fb(Qp[cur][tRow + ar    ][k0 + ac + 4]);
            const unsigned a3 = fb(Qp[cur][tRow + ar + 8][k0 + ac + 4]);
#pragma unroll
            for (int nt = 0; nt < 4; nt++) {
                const int nc = jCol + nt * 8 + ar;
                const unsigned b0 = fb(Cs[cur][k0 + ac    ][nc]);
                const unsigned b1 = fb(Cs[cur][k0 + ac + 4][nc]);
                mma_tf32(tacc[nt], a0, a1, a2, a3, b0, b1);
            }
        }

        const float z0 = 1.0f / (dsum[cur][tRow + ar    ] + EPSZ);
        const float z1 = 1.0f / (dsum[cur][tRow + ar + 8] + EPSZ);
#pragma unroll
        for (int nt = 0; nt < 4; nt++) {
            acc[nt][0] += z0 * tacc[nt][0];
            acc[nt][1] += z0 * tacc[nt][1];
            acc[nt][2] += z1 * tacc[nt][2];
            acc[nt][3] += z1 * tacc[nt][3];
        }
    }

#pragma unroll
    for (int nt = 0; nt < 4; nt++) {
        const int col = jCol + nt * 8 + 2 * ac;
        const float bj0 = b_out[col], bj1 = b_out[col + 1];
        const int r0 = t0g + tRow + ar;
        *(float2*)(out + (size_t)r0 * DD + col) =
            make_float2(acc[nt][0] + bj0, acc[nt][1] + bj1);
        *(float2*)(out + (size_t)(r0 + 8) * DD + col) =
            make_float2(acc[nt][2] + bj0, acc[nt][3] + bj1);
    }
}

// ---------------------------------------------------------------------------
extern "C" void kernel_launch(void* const* d_in, const int* in_sizes, int n_in,
                              void* d_out, int out_size)
{
    const float* q  = (const float*)d_in[0];
    const float* k  = (const float*)d_in[1];
    const float* v  = (const float*)d_in[2];
    const float* W  = (const float*)d_in[3];
    const float* bo = (const float*)d_in[4];
    float* out = (float*)d_out;

    kv_partial_kernel<<<BH * CH, 256>>>(k, v);
    fold_kernel<<<BH, 256>>>(W);
    out_kernel<<<(BB * NN) / 64, 256>>>(q, bo, out);
}

// round 7
// speedup vs baseline: 1.1270x; 1.1270x over previous
#include <cuda_runtime.h>

#define BB 4
#define NN 4096
#define HH 16
#define DD 64
#define HD (HH*DD)          // 1024
#define BH (BB*HH)          // 64
#define CH 16
#define CHTOK (NN/CH)       // 256
#define EPSZ 1e-6f
#define NTILE (BB*NN/64)    // 256 token tiles

#define KVSTR 72            // ==8 mod 32: conflict-free frags
#define QSTR  68            // ==4 mod 32
#define CSTR  72

__device__ float g_KVpart[CH*BH*DD*DD];   // 16 MB
__device__ float g_KSpart[CH*BH*DD];
__device__ float g_C[BH*DD*DD];           // tf32-pre-rounded
__device__ float g_Ksum[BH*DD];
__device__ float g_Opart[2][BB*NN*DD];    // 8 MB: per-head-group partial outputs

__device__ __forceinline__ float phi(float x) { return x > 0.0f ? x + 1.0f : __expf(x); }

__device__ __forceinline__ float tf32r(float x) {
    unsigned u;
    asm("cvt.rna.tf32.f32 %0, %1;" : "=r"(u) : "f"(x));
    return __uint_as_float(u);
}
__device__ __forceinline__ float4 phi4(float4 v) {
    float4 r; r.x = phi(v.x); r.y = phi(v.y); r.z = phi(v.z); r.w = phi(v.w);
    return r;
}
__device__ __forceinline__ float4 r4(float4 v) {
    float4 r; r.x = tf32r(v.x); r.y = tf32r(v.y); r.z = tf32r(v.z); r.w = tf32r(v.w);
    return r;
}

__device__ __forceinline__ void mma_tf32(float c[4],
    unsigned a0, unsigned a1, unsigned a2, unsigned a3,
    unsigned b0, unsigned b1)
{
    asm volatile(
        "mma.sync.aligned.m16n8k8.row.col.f32.tf32.tf32.f32 "
        "{%0,%1,%2,%3},{%4,%5,%6,%7},{%8,%9},{%0,%1,%2,%3};"
        : "+f"(c[0]), "+f"(c[1]), "+f"(c[2]), "+f"(c[3])
        : "r"(a0), "r"(a1), "r"(a2), "r"(a3), "r"(b0), "r"(b1));
}
__device__ __forceinline__ unsigned fb(float x) { return __float_as_uint(x); }

__device__ __forceinline__ void cpa16(void* smem, const void* g) {
    unsigned s = (unsigned)__cvta_generic_to_shared(smem);
    asm volatile("cp.async.ca.shared.global [%0], [%1], 16;" :: "r"(s), "l"(g));
}
#define CP_COMMIT() asm volatile("cp.async.commit_group;")
#define CP_WAIT(n)  asm volatile("cp.async.wait_group %0;" :: "n"(n))

// ---------------------------------------------------------------------------
// Phase 1: partial KV[d][m] = sum_t phi(K[t][d]) * V[t][m], tf32 MMA.
// R5 pipeline shape (commit-at-top, wait(1), 2 barriers) + register Ksum.
// 1024 blocks x 256 threads.
// ---------------------------------------------------------------------------
__global__ __launch_bounds__(256) void kv_partial_kernel(
    const float* __restrict__ key, const float* __restrict__ value)
{
    __shared__ float Ks[2][32][KVSTR];
    __shared__ float Vs[2][32][KVSTR];
    __shared__ float kpart[16][64];

    const int bx  = blockIdx.x;
    const int c   = bx % CH;
    const int bh  = bx / CH;
    const int b   = bh / HH;
    const int h   = bh % HH;
    const int tid = threadIdx.x;
    const int lane = tid & 31, warp = tid >> 5;
    const int dRow = (warp & 3) * 16;
    const int mCol = (warp >> 2) * 32;
    const int ar = lane >> 2;
    const int ac = lane & 3;

    const int t0i = tid >> 4;        // 0..15
    const int t1i = t0i + 16;
    const int d4  = (tid & 15) * 4;

    const int n0 = c * CHTOK;
    const size_t gbase = (size_t)(b * NN + n0) * HD + h * DD + d4;
    const float* kp0 = key   + gbase + (size_t)t0i * HD;
    const float* kp1 = key   + gbase + (size_t)t1i * HD;
    const float* vp0 = value + gbase + (size_t)t0i * HD;
    const float* vp1 = value + gbase + (size_t)t1i * HD;

    float acc[4][4];
#pragma unroll
    for (int nt = 0; nt < 4; nt++)
#pragma unroll
        for (int j = 0; j < 4; j++) acc[nt][j] = 0.0f;

    float4 ks4 = make_float4(0.f, 0.f, 0.f, 0.f);

    // prologue: tile 0 -> stage 0
    cpa16(&Ks[0][t0i][d4], kp0);
    cpa16(&Ks[0][t1i][d4], kp1);
    cpa16(&Vs[0][t0i][d4], vp0);
    cpa16(&Vs[0][t1i][d4], vp1);
    CP_COMMIT();

    const int NT = CHTOK / 32;
    for (int tile = 0; tile < NT; tile++) {
        const int cur = tile & 1;
        if (tile + 1 < NT) {
            const size_t off = (size_t)(tile + 1) * 32 * HD;
            const int nxt = cur ^ 1;
            cpa16(&Ks[nxt][t0i][d4], kp0 + off);
            cpa16(&Ks[nxt][t1i][d4], kp1 + off);
            cpa16(&Vs[nxt][t0i][d4], vp0 + off);
            cpa16(&Vs[nxt][t1i][d4], vp1 + off);
            CP_COMMIT();
            CP_WAIT(1);
        } else {
            CP_WAIT(0);
        }

        // RMW convert own chunks; accumulate Ksum from registers
        {
            const float4 p0 = phi4(*(const float4*)&Ks[cur][t0i][d4]);
            const float4 p1 = phi4(*(const float4*)&Ks[cur][t1i][d4]);
            *(float4*)&Ks[cur][t0i][d4] = r4(p0);
            *(float4*)&Ks[cur][t1i][d4] = r4(p1);
            ks4.x += p0.x + p1.x; ks4.y += p0.y + p1.y;
            ks4.z += p0.z + p1.z; ks4.w += p0.w + p1.w;
            *(float4*)&Vs[cur][t0i][d4] = r4(*(const float4*)&Vs[cur][t0i][d4]);
            *(float4*)&Vs[cur][t1i][d4] = r4(*(const float4*)&Vs[cur][t1i][d4]);
        }
        __syncthreads();

#pragma unroll
        for (int kk = 0; kk < 4; kk++) {
            const int k0 = kk * 8;
            const unsigned a0 = fb(Ks[cur][k0 + ac    ][dRow + ar    ]);
            const unsigned a1 = fb(Ks[cur][k0 + ac    ][dRow + ar + 8]);
            const unsigned a2 = fb(Ks[cur][k0 + ac + 4][dRow + ar    ]);
            const unsigned a3 = fb(Ks[cur][k0 + ac + 4][dRow + ar + 8]);
#pragma unroll
            for (int nt = 0; nt < 4; nt++) {
                const int nc = mCol + nt * 8 + ar;
                const unsigned b0 = fb(Vs[cur][k0 + ac    ][nc]);
                const unsigned b1 = fb(Vs[cur][k0 + ac + 4][nc]);
                mma_tf32(acc[nt], a0, a1, a2, a3, b0, b1);
            }
        }
        __syncthreads();
    }

    *(float4*)&kpart[t0i][d4] = ks4;
    __syncthreads();
    if (tid < 64) {
        float s = 0.0f;
#pragma unroll
        for (int r = 0; r < 16; r++) s += kpart[r][tid];
        g_KSpart[(c * BH + bh) * DD + tid] = s;
    }

    float* outp = g_KVpart + (size_t)(c * BH + bh) * DD * DD;
#pragma unroll
    for (int nt = 0; nt < 4; nt++) {
        const int col = mCol + nt * 8 + 2 * ac;
        const int r0  = dRow + ar;
        *(float2*)(outp + r0 * DD + col)       = make_float2(acc[nt][0], acc[nt][1]);
        *(float2*)(outp + (r0 + 8) * DD + col) = make_float2(acc[nt][2], acc[nt][3]);
    }
}

// ---------------------------------------------------------------------------
// Phase 1.5: fold, split by d-quarter. 256 blocks (bh*4 + dq) x 256 threads.
// Each block: reduce 16 d-rows of partials, GEMM vs W slice, store tf32 C.
// ---------------------------------------------------------------------------
__global__ __launch_bounds__(256) void fold_kernel(const float* __restrict__ W_out)
{
    __shared__ float KVq[16][64];
    __shared__ float Ws[64][68];

    const int bh  = blockIdx.x >> 2;
    const int dq  = blockIdx.x & 3;
    const int h   = bh % HH;
    const int d0  = dq * 16;
    const int tid = threadIdx.x;

    // reduce partials for rows d0..d0+15 (16x64 floats = 256 float4)
    {
        const int lin = tid * 4;                 // float offset in 16x64 slab
        const int d = lin >> 6, m = lin & 63;
        float4 s = make_float4(0.f, 0.f, 0.f, 0.f);
#pragma unroll
        for (int cc = 0; cc < CH; cc++) {
            const float4 p = *(const float4*)(g_KVpart +
                (size_t)(cc * BH + bh) * DD * DD + (d0 + d) * DD + m);
            s.x += p.x; s.y += p.y; s.z += p.z; s.w += p.w;
        }
        *(float4*)&KVq[d][m] = s;
    }
    // load W slice: Ws[j][m] = W_out[j*HD + h*64 + m]
#pragma unroll
    for (int i = 0; i < 4; i++) {
        const int lin = (tid + i * 256) * 4;
        const int j = lin >> 6, m = lin & 63;
        *(float4*)&Ws[j][m] = *(const float4*)(W_out + (size_t)j * HD + h * DD + m);
    }
    if (dq == 0 && tid < 64) {
        float s = 0.0f;
#pragma unroll
        for (int cc = 0; cc < CH; cc++) s += g_KSpart[(cc * BH + bh) * DD + tid];
        g_Ksum[bh * DD + tid] = s;
    }
    __syncthreads();

    // GEMM: C[d0+d][j] = sum_m KVq[d][m] * Ws[j][m]; thread owns (d, j4..j4+3)
    const int d  = tid >> 4;
    const int j4 = (tid & 15) * 4;
    float a0 = 0.f, a1 = 0.f, a2 = 0.f, a3 = 0.f;
#pragma unroll 8
    for (int m = 0; m < 64; m++) {
        const float a = KVq[d][m];
        a0 += a * Ws[j4    ][m];
        a1 += a * Ws[j4 + 1][m];
        a2 += a * Ws[j4 + 2][m];
        a3 += a * Ws[j4 + 3][m];
    }
    float* cp = g_C + (size_t)bh * DD * DD + (d0 + d) * DD + j4;
    *(float4*)cp = make_float4(tf32r(a0), tf32r(a1), tf32r(a2), tf32r(a3));
}

// ---------------------------------------------------------------------------
// Phase 2: head-group split (G=2). Block = (token tile, head group of 8).
// Writes fp32 partial (no bias) to g_Opart. R5-style register prefetch.
// 512 blocks x 256 threads.
// ---------------------------------------------------------------------------
__global__ __launch_bounds__(256) void out_kernel(const float* __restrict__ query)
{
    __shared__ float Qp[64][QSTR];
    __shared__ float Cs[64][CSTR];
    __shared__ float dsum[64];

    const int blk  = blockIdx.x;
    const int tile = blk >> 1;
    const int grp  = blk & 1;
    const int b    = tile >> 6;              // NN/64 = 64 tiles per batch
    const int t0g  = tile * 64;
    const int h0   = grp * 8;
    const int tid  = threadIdx.x;
    const int lane = tid & 31, warp = tid >> 5;
    const int tRow = (warp & 3) * 16;
    const int jCol = (warp >> 2) * 32;
    const int ar = lane >> 2;
    const int ac = lane & 3;

    const int ct  = tid >> 4;        // 0..15
    const int cd4 = (tid & 15) * 4;

    const float* qbase = query + (size_t)(t0g + ct) * HD + h0 * DD + cd4;
    const float* cbase = g_C + (size_t)(b * HH + h0) * DD * DD + ct * DD + cd4;
    const float* kbase = g_Ksum + (b * HH + h0) * DD + cd4;

    float acc[4][4];
#pragma unroll
    for (int nt = 0; nt < 4; nt++)
#pragma unroll
        for (int j = 0; j < 4; j++) acc[nt][j] = 0.0f;

    float4 qbuf[4], cbuf[4], ksv;
#pragma unroll
    for (int i = 0; i < 4; i++) {
        qbuf[i] = *(const float4*)(qbase + (size_t)i * 16 * HD);
        cbuf[i] = *(const float4*)(cbase + i * 16 * DD);
    }
    ksv = *(const float4*)(kbase);

    for (int hh = 0; hh < 8; hh++) {
        // store phase: phi+cvt Q, store C, per-token dot via shfl
#pragma unroll
        for (int i = 0; i < 4; i++) {
            const int t = ct + i * 16;
            const float4 praw = phi4(qbuf[i]);
            *(float4*)&Qp[t][cd4] = r4(praw);
            *(float4*)&Cs[t][cd4] = cbuf[i];   // C pre-rounded by fold
            float partial = praw.x * ksv.x + praw.y * ksv.y +
                            praw.z * ksv.z + praw.w * ksv.w;
#pragma unroll
            for (int off = 8; off >= 1; off >>= 1)
                partial += __shfl_xor_sync(0xffffffffu, partial, off);
            if ((lane & 15) == 0) dsum[t] = partial;
        }
        __syncthreads();

        // prefetch next head during MMA
        if (hh < 7) {
#pragma unroll
            for (int i = 0; i < 4; i++) {
                qbuf[i] = *(const float4*)(qbase + (hh + 1) * DD + (size_t)i * 16 * HD);
                cbuf[i] = *(const float4*)(cbase + (size_t)(hh + 1) * DD * DD + i * 16 * DD);
            }
            ksv = *(const float4*)(kbase + (hh + 1) * DD);
        }

        float tacc[4][4];
#pragma unroll
        for (int nt = 0; nt < 4; nt++)
#pragma unroll
            for (int j = 0; j < 4; j++) tacc[nt][j] = 0.0f;

#pragma unroll
        for (int kk = 0; kk < 8; kk++) {
            const int k0 = kk * 8;
            const unsigned a0 = fb(Qp[tRow + ar    ][k0 + ac    ]);
            const unsigned a1 = fb(Qp[tRow + ar + 8][k0 + ac    ]);
            const unsigned a2 = fb(Qp[tRow + ar    ][k0 + ac + 4]);
            const unsigned a3 = fb(Qp[tRow + ar + 8][k0 + ac + 4]);
#pragma unroll
            for (int nt = 0; nt < 4; nt++) {
                const int nc = jCol + nt * 8 + ar;
                const unsigned b0 = fb(Cs[k0 + ac    ][nc]);
                const unsigned b1 = fb(Cs[k0 + ac + 4][nc]);
                mma_tf32(tacc[nt], a0, a1, a2, a3, b0, b1);
            }
        }

        const float z0 = 1.0f / (dsum[tRow + ar    ] + EPSZ);
        const float z1 = 1.0f / (dsum[tRow + ar + 8] + EPSZ);
#pragma unroll
        for (int nt = 0; nt < 4; nt++) {
            acc[nt][0] += z0 * tacc[nt][0];
            acc[nt][1] += z0 * tacc[nt][1];
            acc[nt][2] += z1 * tacc[nt][2];
            acc[nt][3] += z1 * tacc[nt][3];
        }
        __syncthreads();
    }

    float* op = g_Opart[grp];
#pragma unroll
    for (int nt = 0; nt < 4; nt++) {
        const int col = jCol + nt * 8 + 2 * ac;
        const int r0 = t0g + tRow + ar;
        *(float2*)(op + (size_t)r0 * DD + col) =
            make_float2(acc[nt][0], acc[nt][1]);
        *(float2*)(op + (size_t)(r0 + 8) * DD + col) =
            make_float2(acc[nt][2], acc[nt][3]);
    }
}

// ---------------------------------------------------------------------------
// Phase 3: out = part0 + part1 + bias. 1024 blocks x 256 threads, float4.
// ---------------------------------------------------------------------------
__global__ __launch_bounds__(256) void reduce_kernel(
    const float* __restrict__ b_out, float* __restrict__ out)
{
    const int idx = blockIdx.x * 256 + threadIdx.x;     // float4 index
    const float4 a = *(const float4*)(g_Opart[0] + (size_t)idx * 4);
    const float4 c = *(const float4*)(g_Opart[1] + (size_t)idx * 4);
    const float4 bv = *(const float4*)(b_out + ((idx & 15) << 2));
    float4 r;
    r.x = a.x + c.x + bv.x; r.y = a.y + c.y + bv.y;
    r.z = a.z + c.z + bv.z; r.w = a.w + c.w + bv.w;
    *(float4*)(out + (size_t)idx * 4) = r;
}

// ---------------------------------------------------------------------------
extern "C" void kernel_launch(void* const* d_in, const int* in_sizes, int n_in,
                              void* d_out, int out_size)
{
    const float* q  = (const float*)d_in[0];
    const float* k  = (const float*)d_in[1];
    const float* v  = (const float*)d_in[2];
    const float* W  = (const float*)d_in[3];
    const float* bo = (const float*)d_in[4];
    float* out = (float*)d_out;

    kv_partial_kernel<<<BH * CH, 256>>>(k, v);
    fold_kernel<<<BH * 4, 256>>>(W);
    out_kernel<<<NTILE * 2, 256>>>(q);
    reduce_kernel<<<(BB * NN * DD) / (4 * 256), 256>>>(bo, out);
}

// round 9
// speedup vs baseline: 1.2067x; 1.0708x over previous
#include <cuda_runtime.h>

#define BB 4
#define NN 4096
#define HH 16
#define DD 64
#define HD (HH*DD)          // 1024
#define BH (BB*HH)          // 64
#define CH 16
#define CHTOK (NN/CH)       // 256
#define EPSZ 1e-6f
#define NTILE (BB*NN/64)    // 256 token tiles

#define KVSTR 72            // ==8 mod 32: conflict-free frags
#define QSTR  68            // ==4 mod 32
#define CSTR  72

__device__ float g_KVpart[CH*BH*DD*DD];   // 16 MB
__device__ float g_KSpart[CH*BH*DD];
__device__ float g_C[BH*DD*DD];           // tf32-rna-pre-rounded
__device__ float g_Ksum[BH*DD];

__device__ __forceinline__ float phi(float x) { return x > 0.0f ? x + 1.0f : __expf(x); }

__device__ __forceinline__ float tf32r(float x) {
    unsigned u;
    asm("cvt.rna.tf32.f32 %0, %1;" : "=r"(u) : "f"(x));
    return __uint_as_float(u);
}
__device__ __forceinline__ float4 phi4(float4 v) {
    float4 r; r.x = phi(v.x); r.y = phi(v.y); r.z = phi(v.z); r.w = phi(v.w);
    return r;
}
__device__ __forceinline__ float4 r4(float4 v) {
    float4 r; r.x = tf32r(v.x); r.y = tf32r(v.y); r.z = tf32r(v.z); r.w = tf32r(v.w);
    return r;
}

__device__ __forceinline__ void mma_tf32(float c[4],
    unsigned a0, unsigned a1, unsigned a2, unsigned a3,
    unsigned b0, unsigned b1)
{
    asm volatile(
        "mma.sync.aligned.m16n8k8.row.col.f32.tf32.tf32.f32 "
        "{%0,%1,%2,%3},{%4,%5,%6,%7},{%8,%9},{%0,%1,%2,%3};"
        : "+f"(c[0]), "+f"(c[1]), "+f"(c[2]), "+f"(c[3])
        : "r"(a0), "r"(a1), "r"(a2), "r"(a3), "r"(b0), "r"(b1));
}
__device__ __forceinline__ unsigned fb(float x) { return __float_as_uint(x); }

__device__ __forceinline__ void cpa16(void* smem, const void* g) {
    unsigned s = (unsigned)__cvta_generic_to_shared(smem);
    asm volatile("cp.async.ca.shared.global [%0], [%1], 16;" :: "r"(s), "l"(g));
}
#define CP_COMMIT() asm volatile("cp.async.commit_group;")
#define CP_WAIT(n)  asm volatile("cp.async.wait_group %0;" :: "n"(n))
#define BAR_GRP(id) asm volatile("bar.sync %0, 128;" :: "r"(id) : "memory")

// ---------------------------------------------------------------------------
// Phase 1: partial KV[d][m] = sum_t phi(K[t][d]) * V[t][m], tf32 MMA.
// R5 pipeline (commit-at-top, wait(1), 2 barriers); K RMW = phi + rna,
// V RMW = rna; register Ksum. 1024 blocks x 256 threads.
// ---------------------------------------------------------------------------
__global__ __launch_bounds__(256) void kv_partial_kernel(
    const float* __restrict__ key, const float* __restrict__ value)
{
    __shared__ float Ks[2][32][KVSTR];
    __shared__ float Vs[2][32][KVSTR];
    __shared__ float kpart[16][64];

    const int bx  = blockIdx.x;
    const int c   = bx % CH;
    const int bh  = bx / CH;
    const int b   = bh / HH;
    const int h   = bh % HH;
    const int tid = threadIdx.x;
    const int lane = tid & 31, warp = tid >> 5;
    const int dRow = (warp & 3) * 16;
    const int mCol = (warp >> 2) * 32;
    const int ar = lane >> 2;
    const int ac = lane & 3;

    const int t0i = tid >> 4;        // 0..15
    const int t1i = t0i + 16;
    const int d4  = (tid & 15) * 4;

    const int n0 = c * CHTOK;
    const size_t gbase = (size_t)(b * NN + n0) * HD + h * DD + d4;
    const float* kp0 = key   + gbase + (size_t)t0i * HD;
    const float* kp1 = key   + gbase + (size_t)t1i * HD;
    const float* vp0 = value + gbase + (size_t)t0i * HD;
    const float* vp1 = value + gbase + (size_t)t1i * HD;

    float acc[4][4];
#pragma unroll
    for (int nt = 0; nt < 4; nt++)
#pragma unroll
        for (int j = 0; j < 4; j++) acc[nt][j] = 0.0f;

    float4 ks4 = make_float4(0.f, 0.f, 0.f, 0.f);

    cpa16(&Ks[0][t0i][d4], kp0);
    cpa16(&Ks[0][t1i][d4], kp1);
    cpa16(&Vs[0][t0i][d4], vp0);
    cpa16(&Vs[0][t1i][d4], vp1);
    CP_COMMIT();

    const int NT = CHTOK / 32;
    for (int tile = 0; tile < NT; tile++) {
        const int cur = tile & 1;
        if (tile + 1 < NT) {
            const size_t off = (size_t)(tile + 1) * 32 * HD;
            const int nxt = cur ^ 1;
            cpa16(&Ks[nxt][t0i][d4], kp0 + off);
            cpa16(&Ks[nxt][t1i][d4], kp1 + off);
            cpa16(&Vs[nxt][t0i][d4], vp0 + off);
            cpa16(&Vs[nxt][t1i][d4], vp1 + off);
            CP_COMMIT();
            CP_WAIT(1);
        } else {
            CP_WAIT(0);
        }

        // RMW convert own chunks; accumulate Ksum from registers
        {
            const float4 p0 = phi4(*(const float4*)&Ks[cur][t0i][d4]);
            const float4 p1 = phi4(*(const float4*)&Ks[cur][t1i][d4]);
            *(float4*)&Ks[cur][t0i][d4] = r4(p0);
            *(float4*)&Ks[cur][t1i][d4] = r4(p1);
            ks4.x += p0.x + p1.x; ks4.y += p0.y + p1.y;
            ks4.z += p0.z + p1.z; ks4.w += p0.w + p1.w;
            *(float4*)&Vs[cur][t0i][d4] = r4(*(const float4*)&Vs[cur][t0i][d4]);
            *(float4*)&Vs[cur][t1i][d4] = r4(*(const float4*)&Vs[cur][t1i][d4]);
        }
        __syncthreads();

#pragma unroll
        for (int kk = 0; kk < 4; kk++) {
            const int k0 = kk * 8;
            const unsigned a0 = fb(Ks[cur][k0 + ac    ][dRow + ar    ]);
            const unsigned a1 = fb(Ks[cur][k0 + ac    ][dRow + ar + 8]);
            const unsigned a2 = fb(Ks[cur][k0 + ac + 4][dRow + ar    ]);
            const unsigned a3 = fb(Ks[cur][k0 + ac + 4][dRow + ar + 8]);
#pragma unroll
            for (int nt = 0; nt < 4; nt++) {
                const int nc = mCol + nt * 8 + ar;
                const unsigned b0 = fb(Vs[cur][k0 + ac    ][nc]);
                const unsigned b1 = fb(Vs[cur][k0 + ac + 4][nc]);
                mma_tf32(acc[nt], a0, a1, a2, a3, b0, b1);
            }
        }
        __syncthreads();
    }

    *(float4*)&kpart[t0i][d4] = ks4;
    __syncthreads();
    if (tid < 64) {
        float s = 0.0f;
#pragma unroll
        for (int r = 0; r < 16; r++) s += kpart[r][tid];
        g_KSpart[(c * BH + bh) * DD + tid] = s;
    }

    float* outp = g_KVpart + (size_t)(c * BH + bh) * DD * DD;
#pragma unroll
    for (int nt = 0; nt < 4; nt++) {
        const int col = mCol + nt * 8 + 2 * ac;
        const int r0  = dRow + ar;
        *(float2*)(outp + r0 * DD + col)       = make_float2(acc[nt][0], acc[nt][1]);
        *(float2*)(outp + (r0 + 8) * DD + col) = make_float2(acc[nt][2], acc[nt][3]);
    }
}

// ---------------------------------------------------------------------------
// Phase 1.5: fold, split by d-quarter; stores C tf32-rna-rounded.
// 256 blocks x 256 threads.
// ---------------------------------------------------------------------------
__global__ __launch_bounds__(256) void fold_kernel(const float* __restrict__ W_out)
{
    __shared__ float KVq[16][64];
    __shared__ float Ws[64][68];

    const int bh  = blockIdx.x >> 2;
    const int dq  = blockIdx.x & 3;
    const int h   = bh % HH;
    const int d0  = dq * 16;
    const int tid = threadIdx.x;

    {
        const int lin = tid * 4;
        const int d = lin >> 6, m = lin & 63;
        float4 s = make_float4(0.f, 0.f, 0.f, 0.f);
#pragma unroll
        for (int cc = 0; cc < CH; cc++) {
            const float4 p = *(const float4*)(g_KVpart +
                (size_t)(cc * BH + bh) * DD * DD + (d0 + d) * DD + m);
            s.x += p.x; s.y += p.y; s.z += p.z; s.w += p.w;
        }
        *(float4*)&KVq[d][m] = s;
    }
#pragma unroll
    for (int i = 0; i < 4; i++) {
        const int lin = (tid + i * 256) * 4;
        const int j = lin >> 6, m = lin & 63;
        *(float4*)&Ws[j][m] = *(const float4*)(W_out + (size_t)j * HD + h * DD + m);
    }
    if (dq == 0 && tid < 64) {
        float s = 0.0f;
#pragma unroll
        for (int cc = 0; cc < CH; cc++) s += g_KSpart[(cc * BH + bh) * DD + tid];
        g_Ksum[bh * DD + tid] = s;
    }
    __syncthreads();

    const int d  = tid >> 4;
    const int j4 = (tid & 15) * 4;
    float a0 = 0.f, a1 = 0.f, a2 = 0.f, a3 = 0.f;
#pragma unroll 8
    for (int m = 0; m < 64; m++) {
        const float a = KVq[d][m];
        a0 += a * Ws[j4    ][m];
        a1 += a * Ws[j4 + 1][m];
        a2 += a * Ws[j4 + 2][m];
        a3 += a * Ws[j4 + 3][m];
    }
    float* cp = g_C + (size_t)bh * DD * DD + (d0 + d) * DD + j4;
    *(float4*)cp = make_float4(tf32r(a0), tf32r(a1), tf32r(a2), tf32r(a3));
}

// ---------------------------------------------------------------------------
// Phase 2: out[t][j] = b[j] + sum_h Z[t,h]*(Qphi[t,h,:] @ C[b,h][:,j]).
// Two independent 4-warp groups (named barriers), each processing its own
// head per pair-iteration (8 iterations). Warp tile 32x32. Z folded into
// the rna-rounded Qp smem store. C via cp.async (pre-rounded, L2-resident);
// Q register-prefetched during MMA. Final smem merge. 256 blocks x 256 thr.
// ---------------------------------------------------------------------------
__global__ __launch_bounds__(256) void out_kernel(
    const float* __restrict__ query, const float* __restrict__ b_out,
    float* __restrict__ out)
{
    __shared__ float Qp[2][64][QSTR];
    __shared__ float Cs[2][64][CSTR];

    const int blk = blockIdx.x;
    const int b   = blk >> 6;               // NN/64 = 64 tiles per batch
    const int t0g = blk * 64;
    const int tid = threadIdx.x;
    const int lane = tid & 31, warp = tid >> 5;
    const int hs   = warp >> 2;             // head slot 0/1
    const int wq   = warp & 3;
    const int mRow = (wq & 1) * 32;
    const int nCol = (wq >> 1) * 32;
    const int ar = lane >> 2;
    const int ac = lane & 3;
    const int barid = 1 + hs;

    const int l   = tid & 127;
    const int rb  = l >> 4;                 // 0..7 row base (stride 8)
    const int cd4 = (l & 15) * 4;

    const float* qbase = query + (size_t)(t0g + rb) * HD + cd4;
    const float* cbase = g_C + (size_t)(b * HH) * DD * DD + rb * DD + cd4;
    const float* kbase = g_Ksum + (b * HH) * DD + cd4;

    float acc[2][4][4];
#pragma unroll
    for (int mi = 0; mi < 2; mi++)
#pragma unroll
        for (int ni = 0; ni < 4; ni++)
#pragma unroll
            for (int j = 0; j < 4; j++) acc[mi][ni][j] = 0.0f;

    float4 qbuf[8];
#pragma unroll
    for (int i = 0; i < 8; i++)
        qbuf[i] = *(const float4*)(qbase + hs * DD + (size_t)i * 8 * HD);

    for (int p = 0; p < 8; p++) {
        const int hd = 2 * p + hs;

        // cp.async C tile for this head (lands during phi/dot phase)
#pragma unroll
        for (int i = 0; i < 8; i++)
            cpa16(&Cs[hs][rb + i * 8][cd4],
                  cbase + (size_t)hd * DD * DD + i * 8 * DD);
        CP_COMMIT();

        const float4 ksv = *(const float4*)(kbase + hd * DD);
        // phi, per-token fp32 dot (shfl over 16-lane half), scale, rna, store
#pragma unroll
        for (int i = 0; i < 8; i++) {
            const float4 pr = phi4(qbuf[i]);
            float dot = pr.x * ksv.x + pr.y * ksv.y + pr.z * ksv.z + pr.w * ksv.w;
#pragma unroll
            for (int off = 8; off >= 1; off >>= 1)
                dot += __shfl_xor_sync(0xffffffffu, dot, off);
            const float z = 1.0f / (dot + EPSZ);
            float4 w; w.x = pr.x * z; w.y = pr.y * z; w.z = pr.z * z; w.w = pr.w * z;
            *(float4*)&Qp[hs][rb + i * 8][cd4] = r4(w);
        }
        CP_WAIT(0);
        BAR_GRP(barid);

        // prefetch next pair's Q during MMA
        if (p < 7) {
#pragma unroll
            for (int i = 0; i < 8; i++)
                qbuf[i] = *(const float4*)(qbase + (hd + 2) * DD + (size_t)i * 8 * HD);
        }

#pragma unroll
        for (int kk = 0; kk < 8; kk++) {
            const int k0 = kk * 8;
            unsigned a[2][4];
#pragma unroll
            for (int mi = 0; mi < 2; mi++) {
                const int r = mRow + mi * 16 + ar;
                a[mi][0] = fb(Qp[hs][r    ][k0 + ac    ]);
                a[mi][1] = fb(Qp[hs][r + 8][k0 + ac    ]);
                a[mi][2] = fb(Qp[hs][r    ][k0 + ac + 4]);
                a[mi][3] = fb(Qp[hs][r + 8][k0 + ac + 4]);
            }
#pragma unroll
            for (int ni = 0; ni < 4; ni++) {
                const int nc = nCol + ni * 8 + ar;
                const unsigned b0 = fb(Cs[hs][k0 + ac    ][nc]);
                const unsigned b1 = fb(Cs[hs][k0 + ac + 4][nc]);
#pragma unroll
                for (int mi = 0; mi < 2; mi++)
                    mma_tf32(acc[mi][ni], a[mi][0], a[mi][1], a[mi][2], a[mi][3], b0, b1);
            }
        }
        BAR_GRP(barid);
    }

    // merge head-group partials: slot1 -> smem, slot0 adds + bias + store
    __syncthreads();
    if (hs == 1) {
#pragma unroll
        for (int mi = 0; mi < 2; mi++)
#pragma unroll
            for (int ni = 0; ni < 4; ni++) {
                const int r = mRow + mi * 16 + ar;
                const int ccol = nCol + ni * 8 + 2 * ac;
                *(float2*)&Cs[0][r    ][ccol] = make_float2(acc[mi][ni][0], acc[mi][ni][1]);
                *(float2*)&Cs[0][r + 8][ccol] = make_float2(acc[mi][ni][2], acc[mi][ni][3]);
            }
    }
    __syncthreads();
    if (hs == 0) {
#pragma unroll
        for (int mi = 0; mi < 2; mi++)
#pragma unroll
            for (int ni = 0; ni < 4; ni++) {
                const int r = mRow + mi * 16 + ar;
                const int ccol = nCol + ni * 8 + 2 * ac;
                const float bj0 = b_out[ccol], bj1 = b_out[ccol + 1];
                const float2 o0 = *(const float2*)&Cs[0][r    ][ccol];
                const float2 o1 = *(const float2*)&Cs[0][r + 8][ccol];
                *(float2*)(out + (size_t)(t0g + r) * DD + ccol) =
                    make_float2(acc[mi][ni][0] + o0.x + bj0, acc[mi][ni][1] + o0.y + bj1);
                *(float2*)(out + (size_t)(t0g + r + 8) * DD + ccol) =
                    make_float2(acc[mi][ni][2] + o1.x + bj0, acc[mi][ni][3] + o1.y + bj1);
            }
    }
}

// ---------------------------------------------------------------------------
extern "C" void kernel_launch(void* const* d_in, const int* in_sizes, int n_in,
                              void* d_out, int out_size)
{
    const float* q  = (const float*)d_in[0];
    const float* k  = (const float*)d_in[1];
    const float* v  = (const float*)d_in[2];
    const float* W  = (const float*)d_in[3];
    const float* bo = (const float*)d_in[4];
    float* out = (float*)d_out;

    kv_partial_kernel<<<BH * CH, 256>>>(k, v);
    fold_kernel<<<BH * 4, 256>>>(W);
    out_kernel<<<NTILE, 256>>>(q, bo, out);
}